// round 10
// baseline (speedup 1.0000x reference)
#include <cuda_runtime.h>
#include <cuda_bf16.h>
#include <cstdint>
#include <cstddef>

#define TB    512
#define HD    128
#define NC    10
#define KT    9            // Taylor terms k=0..8, trunc err ~7.5e-6
#define EPS   1e-5f
#define LDT   272          // tile row stride in BYTES (136 bf16) — conflict-free ldmatrix

// ---- smem byte offsets ----
#define SM_AHI  0                         // A tile [row][k] 128 x 272B
#define SM_ALO  (SM_AHI + 128*LDT)        // lo tile always at hi + 128*LDT
#define SM_WHI  (SM_ALO + 128*LDT)        // W tile [k][n] 128 x 272B  (gmem layout!)
#define SM_WLO  (SM_WHI + 128*LDT)
#define SM_SCR  (SM_WLO + 128*LDT)        // 128 rows * 37 floats (moments / classifier)
#define SM_LN   (SM_SCR + 128*37*4)       // 128 rows * 4 floats
#define SM_WC   (SM_LN  + 128*4*4)        // 1280 floats
#define SM_VEC  (SM_WC  + 1280*4)         // vS[128], gS[128], btS[128], bcS[16], pad
#define SM_TOTAL (SM_VEC + 416*4)

#define LDSM4(r, addr) \
    asm volatile("ldmatrix.sync.aligned.m8n8.x4.shared.b16 {%0,%1,%2,%3}, [%4];" \
        : "=r"((r)[0]), "=r"((r)[1]), "=r"((r)[2]), "=r"((r)[3]) : "r"(addr))

#define LDSM4T(r, addr) \
    asm volatile("ldmatrix.sync.aligned.m8n8.x4.trans.shared.b16 {%0,%1,%2,%3}, [%4];" \
        : "=r"((r)[0]), "=r"((r)[1]), "=r"((r)[2]), "=r"((r)[3]) : "r"(addr))

#define MMA16816(c, a, b) \
    asm volatile("mma.sync.aligned.m16n8k16.row.col.f32.bf16.bf16.f32 " \
        "{%0,%1,%2,%3},{%4,%5,%6,%7},{%8,%9},{%0,%1,%2,%3};" \
        : "+f"((c)[0]), "+f"((c)[1]), "+f"((c)[2]), "+f"((c)[3]) \
        : "r"((a)[0]), "r"((a)[1]), "r"((a)[2]), "r"((a)[3]), "r"((b)[0]), "r"((b)[1]))

// accumulator D layout (m16n8): slot s=0 -> row rw+quad (c0,c1), s=1 -> row rw+8+quad (c2,c3)
#define ACCV(s, i) acc[(i) >> 1][(((s) & 1) << 1) | ((i) & 1)]

__device__ __forceinline__ uint32_t smem_u32(const void* p) {
    uint32_t a;
    asm("{ .reg .u64 t; cvta.to.shared.u64 t, %1; cvt.u32.u64 %0, t; }" : "=r"(a) : "l"(p));
    return a;
}
__device__ __forceinline__ float fast_tanh(float v) {
    float r;
    asm("tanh.approx.f32 %0, %1;" : "=f"(r) : "f"(v));
    return r;
}

// split fp32 pair -> bf16 hi pair + bf16 lo pair; store 4B each to hi tile and hi+128*LDT
__device__ __forceinline__ void split_store2(char* hi_base, uint32_t off, float v0, float v1) {
    __nv_bfloat16 h0 = __float2bfloat16(v0);
    __nv_bfloat16 h1 = __float2bfloat16(v1);
    float r0 = v0 - __bfloat162float(h0);
    float r1 = v1 - __bfloat162float(h1);
    __nv_bfloat162 hp; hp.x = h0; hp.y = h1;
    __nv_bfloat162 lp; lp.x = __float2bfloat16(r0); lp.y = __float2bfloat16(r1);
    *reinterpret_cast<__nv_bfloat162*>(hi_base + off)             = hp;
    *reinterpret_cast<__nv_bfloat162*>(hi_base + off + 128 * LDT) = lp;
}

// split a float4 -> 8B hi + 8B lo stores
__device__ __forceinline__ void split_store4(char* hi_base, uint32_t off, float4 v) {
    __nv_bfloat162 h01, h23, l01, l23;
    h01.x = __float2bfloat16(v.x); h01.y = __float2bfloat16(v.y);
    h23.x = __float2bfloat16(v.z); h23.y = __float2bfloat16(v.w);
    l01.x = __float2bfloat16(v.x - __bfloat162float(h01.x));
    l01.y = __float2bfloat16(v.y - __bfloat162float(h01.y));
    l23.x = __float2bfloat16(v.z - __bfloat162float(h23.x));
    l23.y = __float2bfloat16(v.w - __bfloat162float(h23.y));
    uint2 hp, lp;
    hp.x = *(uint32_t*)&h01; hp.y = *(uint32_t*)&h23;
    lp.x = *(uint32_t*)&l01; lp.y = *(uint32_t*)&l23;
    *reinterpret_cast<uint2*>(hi_base + off)             = hp;
    *reinterpret_cast<uint2*>(hi_base + off + 128 * LDT) = lp;
}

__global__ __launch_bounds__(TB, 1)
void fused_attn_hmma(const float* __restrict__ x,
                     const float* __restrict__ W_in,
                     const float* __restrict__ b_in,
                     const float* __restrict__ W_att,
                     const float* __restrict__ b_att,
                     const float* __restrict__ gamma,
                     const float* __restrict__ beta,
                     const float* __restrict__ W_c,
                     const float* __restrict__ b_c,
                     float* __restrict__ out)
{
    extern __shared__ char sm[];
    float* scr   = (float*)(sm + SM_SCR);
    float* lnscr = (float*)(sm + SM_LN);
    float* wcS   = (float*)(sm + SM_WC);
    float* vS    = (float*)(sm + SM_VEC);
    float* gS    = vS + 128;
    float* btS   = vS + 256;
    float* bcS   = vS + 384;

    const int tid  = threadIdx.x;
    const int w    = tid >> 5;
    const int lane = tid & 31;
    const int quad = lane >> 2;
    const int qt   = lane & 3;
    const int rw   = (w & 7) * 16;       // warp row strip (16 rows)
    const int strip = w >> 3;            // 0 or 1
    const int cwS  = strip * 64;         // warp col strip (64 cols)
    const int row0 = blockIdx.x * 128;

    const uint32_t smb = smem_u32(sm);
    // A ldmatrix lane offset (row-major A [row][k])
    const uint32_t aOff = smb + (uint32_t)((rw + (lane & 15)) * LDT + (lane >> 4) * 16);
    // B trans-ldmatrix lane offset (W stored [k][n]):
    // matrix mi = lane>>3: {k0-7@n0, k8-15@n0, k0-7@n0+8, k8-15@n0+8}
    const int mi  = lane >> 3;
    const int bk  = (lane & 7) + ((mi & 1) << 3);   // k-row 0..15 within kstep
    const int bn  = (mi >> 1) << 3;                 // n col offset 0 or 8
    const uint32_t bOff = smb + (uint32_t)(bk * LDT + (cwS + bn) * 2);

    // ---- stage x -> A tiles (bf16 hi/lo) ----
    for (int i = tid; i < 128 * 64; i += TB) {
        const int r = i >> 6, c2 = (i & 63) * 2;
        const float2 v = *(const float2*)(x + (size_t)(row0 + r) * HD + c2);
        split_store2(sm + SM_AHI, (uint32_t)(r * LDT + c2 * 2), v.x, v.y);
    }
    // ---- stage W (coalesced, NO transpose: tile[k][n] = W[k][n]) ----
    auto stageW = [&](const float* Wg) {
        #pragma unroll
        for (int j = 0; j < 8; j++) {
            const int i  = tid + j * TB;          // 0..4095
            const int k  = i >> 5;
            const int n4 = (i & 31) * 4;
            const float4 v = *(const float4*)(Wg + (size_t)k * HD + n4);
            split_store4(sm + SM_WHI, (uint32_t)(k * LDT + n4 * 2), v);
        }
    };
    stageW(W_in);
    for (int i = tid; i < HD * NC; i += TB) wcS[i] = W_c[i];
    if (tid < 128) vS[tid] = b_in[tid];
    if (tid < 16)  bcS[tid] = (tid < NC) ? b_c[tid] : 0.f;
    __syncthreads();

    const float invf[KT] = {1.f, 1.f, 0.5f, 1.f/6.f, 1.f/24.f, 1.f/120.f,
                            1.f/720.f, 1.f/5040.f, 1.f/40320.f};

    float acc[8][4];
    float h[32];

    // triple-product split-precision GEMM into fp32 accum (warp tile 16x64)
    auto gemm3 = [&]() {
        #pragma unroll
        for (int nt = 0; nt < 8; nt++)
            #pragma unroll
            for (int c = 0; c < 4; c++) acc[nt][c] = 0.f;
        const uint32_t abases[3] = {SM_AHI, SM_AHI, SM_ALO};
        const uint32_t bbases[3] = {SM_WHI, SM_WLO, SM_WHI};
        #pragma unroll
        for (int p = 0; p < 3; p++) {
            #pragma unroll
            for (int kst = 0; kst < 8; kst++) {
                uint32_t a0[4];
                LDSM4(a0, aOff + abases[p] + kst * 32);
                uint32_t bfr[8][2];
                #pragma unroll
                for (int q = 0; q < 4; q++) {
                    uint32_t t4[4];
                    LDSM4T(t4, bOff + bbases[p] + kst * 16 * LDT + q * 32);
                    bfr[2*q][0]   = t4[0]; bfr[2*q][1]   = t4[1];
                    bfr[2*q+1][0] = t4[2]; bfr[2*q+1][1] = t4[3];
                }
                #pragma unroll
                for (int nt = 0; nt < 8; nt++)
                    MMA16816(acc[nt], a0, bfr[nt]);
            }
        }
    };

    auto writeH = [&]() {
        #pragma unroll
        for (int s = 0; s < 2; s++) {
            const int row = rw + s * 8 + quad;
            #pragma unroll
            for (int ip = 0; ip < 8; ip++) {
                const int col = cwS + ip * 8 + qt * 2;
                split_store2(sm + SM_AHI, (uint32_t)(row * LDT + col * 2),
                             h[s * 16 + 2 * ip], h[s * 16 + 2 * ip + 1]);
            }
        }
    };

    // ---- round 0: h = x @ W_in + b_in ----
    gemm3();
    {
        float bias_r[16];
        #pragma unroll
        for (int i = 0; i < 16; i++) bias_r[i] = vS[cwS + (i >> 1) * 8 + qt * 2 + (i & 1)];
        #pragma unroll
        for (int s = 0; s < 2; s++)
            #pragma unroll
            for (int i = 0; i < 16; i++) h[s * 16 + i] = ACCV(s, i) + bias_r[i];
    }
    __syncthreads();          // all ldmatrix reads of A/W done
    writeH();
    stageW(W_att);
    if (tid < 128) { vS[tid] = b_att[tid]; gS[tid] = gamma[tid]; btS[tid] = beta[tid]; }
    __syncthreads();

    // ---- 3 attention layers ----
    for (int l = 0; l < 3; ++l) {
        gemm3();

        // u = tanh(pre + bias), overwrite acc
        {
            float bias_r[16];
            #pragma unroll
            for (int i = 0; i < 16; i++) bias_r[i] = vS[cwS + (i >> 1) * 8 + qt * 2 + (i & 1)];
            #pragma unroll
            for (int s = 0; s < 2; s++)
                #pragma unroll
                for (int i = 0; i < 16; i++)
                    ACCV(s, i) = fast_tanh(ACCV(s, i) + bias_r[i]);
        }

        // Taylor-moment partials per row slot; quad-reduce; write strip moments
        #pragma unroll
        for (int s = 0; s < 2; s++) {
            float z[KT], m[KT];
            #pragma unroll
            for (int k = 0; k < KT; k++) { z[k] = 0.f; m[k] = 0.f; }
            z[0] = 16.f;
            #pragma unroll
            for (int i = 0; i < 16; i++) {
                const float uj = ACCV(s, i);
                const float hj = h[s * 16 + i];
                float p = uj;
                m[0] += hj;
                z[1] += p; m[1] += p * hj;
                #pragma unroll
                for (int k = 2; k < KT; k++) { p *= uj; z[k] += p; m[k] += p * hj; }
            }
            #pragma unroll
            for (int k = 0; k < KT; k++) {
                z[k] += __shfl_xor_sync(0xffffffffu, z[k], 1);
                z[k] += __shfl_xor_sync(0xffffffffu, z[k], 2);
                m[k] += __shfl_xor_sync(0xffffffffu, m[k], 1);
                m[k] += __shfl_xor_sync(0xffffffffu, m[k], 2);
            }
            const int row = rw + s * 8 + quad;
            float* p = scr + row * 37 + strip * 18;
            #pragma unroll
            for (int k = 0; k < KT; k++)
                if ((k & 3) == qt) { p[k] = z[k]; p[KT + k] = m[k]; }
        }
        __syncthreads();      // sync1: moments ready; gemm3 W reads done

        // overlap: stage next layer's W while this layer's eval math runs
        if (l < 2) stageW(W_att + (size_t)(l + 1) * HD * HD);

        // combine strips, eval softmax-free output, residual, LN partials
        #pragma unroll
        for (int s = 0; s < 2; s++) {
            const int row = rw + s * 8 + quad;
            const float* p = scr + row * 37;
            float zc[KT], mc[KT];
            #pragma unroll
            for (int k = 0; k < KT; k++) {
                zc[k] = (p[k]      + p[18 + k])      * invf[k];
                mc[k] = (p[KT + k] + p[18 + KT + k]) * invf[k];
            }
            float s1 = 0.f, s2 = 0.f;
            #pragma unroll
            for (int i = 0; i < 16; i++) {
                const float ui = ACCV(s, i);
                float sd = zc[KT - 1], td = mc[KT - 1];
                #pragma unroll
                for (int k = KT - 2; k >= 0; --k) {
                    sd = fmaf(sd, ui, zc[k]);
                    td = fmaf(td, ui, mc[k]);
                }
                const float y = h[s * 16 + i] + __fdividef(td, sd);
                s1 += y; s2 += y * y;
                ACCV(s, i) = y;
            }
            s1 += __shfl_xor_sync(0xffffffffu, s1, 1);
            s1 += __shfl_xor_sync(0xffffffffu, s1, 2);
            s2 += __shfl_xor_sync(0xffffffffu, s2, 1);
            s2 += __shfl_xor_sync(0xffffffffu, s2, 2);
            if (qt == 0) {
                lnscr[row * 4 + strip * 2]     = s1;
                lnscr[row * 4 + strip * 2 + 1] = s2;
            }
        }
        __syncthreads();      // sync2: lnscr ready

        // layernorm finalize -> new h
        {
            float g_r[16], bt_r[16];
            #pragma unroll
            for (int i = 0; i < 16; i++) {
                const int c = cwS + (i >> 1) * 8 + qt * 2 + (i & 1);
                g_r[i] = gS[c]; bt_r[i] = btS[c];
            }
            #pragma unroll
            for (int s = 0; s < 2; s++) {
                const int row = rw + s * 8 + quad;
                const float su = lnscr[row * 4]     + lnscr[row * 4 + 2];
                const float ss = lnscr[row * 4 + 1] + lnscr[row * 4 + 3];
                const float mean = su * (1.f / HD);
                const float var  = fmaf(ss, 1.f / HD, -mean * mean);
                const float rinv = rsqrtf(var + EPS);
                #pragma unroll
                for (int i = 0; i < 16; i++)
                    h[s * 16 + i] = (ACCV(s, i) - mean) * rinv * g_r[i] + bt_r[i];
            }
        }

        if (l < 2) {
            writeH();         // A tiles last read before sync1 -> safe
            if (tid < 128) {  // vec reads (gS/btS) done just above; vS read pre-sync1
                vS[tid]  = b_att[(l + 1) * HD + tid];
                gS[tid]  = gamma[(l + 1) * HD + tid];
                btS[tid] = beta[(l + 1) * HD + tid];
            }
            __syncthreads();  // sync3: A/W/vec staged for next gemm3
        }
    }

    // ---- classifier: logits = h @ W_c + b_c ----
    #pragma unroll
    for (int s = 0; s < 2; s++) {
        float ac[NC];
        #pragma unroll
        for (int c = 0; c < NC; c++) ac[c] = 0.f;
        #pragma unroll
        for (int i = 0; i < 16; i++) {
            const float hv = h[s * 16 + i];
            const float* wr = wcS + (cwS + (i >> 1) * 8 + qt * 2 + (i & 1)) * NC;
            #pragma unroll
            for (int c = 0; c < NC; c++) ac[c] = fmaf(hv, wr[c], ac[c]);
        }
        #pragma unroll
        for (int c = 0; c < NC; c++) {
            ac[c] += __shfl_xor_sync(0xffffffffu, ac[c], 1);
            ac[c] += __shfl_xor_sync(0xffffffffu, ac[c], 2);
        }
        const int row = rw + s * 8 + quad;
        #pragma unroll
        for (int c = 0; c < NC; c++)
            if ((c & 3) == qt) scr[row * 37 + strip * 10 + c] = ac[c];
    }
    __syncthreads();
    if (tid < 128) {
        const float* p = scr + tid * 37;
        float* o = out + (size_t)(row0 + tid) * NC;
        #pragma unroll
        for (int c = 0; c < NC; c++) o[c] = p[c] + p[10 + c] + bcS[c];
    }
}

extern "C" void kernel_launch(void* const* d_in, const int* in_sizes, int n_in,
                              void* d_out, int out_size)
{
    (void)in_sizes; (void)n_in; (void)out_size;
    const float* x     = (const float*)d_in[0];
    const float* W_in  = (const float*)d_in[1];
    const float* b_in  = (const float*)d_in[2];
    const float* W_att = (const float*)d_in[3];
    const float* b_att = (const float*)d_in[4];
    const float* gamma = (const float*)d_in[5];
    const float* beta  = (const float*)d_in[6];
    const float* W_c   = (const float*)d_in[7];
    const float* b_c   = (const float*)d_in[8];
    float* out = (float*)d_out;

    cudaFuncSetAttribute(fused_attn_hmma,
                         cudaFuncAttributeMaxDynamicSharedMemorySize, SM_TOTAL);
    fused_attn_hmma<<<16384 / 128, TB, SM_TOTAL>>>(
        x, W_in, b_in, W_att, b_att, gamma, beta, W_c, b_c, out);
}